// round 9
// baseline (speedup 1.0000x reference)
#include <cuda_runtime.h>
#include <cuda_fp16.h>
#include <cstdint>

// out[b,h,i,j] = scores[b,h,i,j] + sum_d q[b,h,i,d] * E[(j-i)+4096, d]
// B=2,H=16,S=2048,D=64.
//
// 64x128 (i,j) tile. G[i,r] = Q(64x64) . E_rows(192x64)^T, j = r + i - 63.
// fp16 mma.sync m16n8k16 band GEMM (warp (mi,nh): m-tile mi, 9 n-tiles from
// nBase = 6-2mi+9nh). R8 profiling: L1tex dominated by the scalar +=-scatter.
// Fix: store G in natural band layout sG[i][r_local], r_local = 8*(9nh+t)+2tig
// (mi-independent, in [0,144), fragment pairs r-adjacent) => 18 predicate-free
// conflict-free st.64 per thread (pitch 152 == 24 mod 32 => half-warp banks
// 24g+2t distinct). Diagonal shift moves to the epilogue READ:
// out[i][j] = scores[i][j] + sG[i][j + 15 - (i&15)]  (lane-stride-1 LDS, cf;
// LDG/STG fully coalesced). No sS buffer, no bulk tail. 75.8KB => 3 CTAs/SM.

#define S_LEN 2048
#define TI 64
#define TJ 128
#define ER 192
#define QPW 36           // Q pitch (u32): mainloop banks 4g+t bijective
#define EPW 36
#define SGP 152          // sG pitch (floats): 152 % 32 == 24 -> cf st.64

#define SMEM_Q_U32 (TI * QPW)            // 2304
#define SMEM_E_U32 (ER * EPW)            // 6912
#define SMEM_G_U32 (TI * SGP)            // 9728
#define SMEM_U32 (SMEM_Q_U32 + SMEM_E_U32 + SMEM_G_U32)
#define SMEM_BYTES (SMEM_U32 * 4)        // 75776

__device__ __forceinline__ void mma_f16(float* c,
                                        uint32_t a0, uint32_t a1,
                                        uint32_t a2, uint32_t a3,
                                        uint32_t b0, uint32_t b1) {
    asm volatile(
        "mma.sync.aligned.m16n8k16.row.col.f32.f16.f16.f32 "
        "{%0,%1,%2,%3}, {%4,%5,%6,%7}, {%8,%9}, {%0,%1,%2,%3};"
        : "+f"(c[0]), "+f"(c[1]), "+f"(c[2]), "+f"(c[3])
        : "r"(a0), "r"(a1), "r"(a2), "r"(a3), "r"(b0), "r"(b1));
}

__device__ __forceinline__ uint32_t pack_h2(float lo, float hi) {
    __half2 h = __floats2half2_rn(lo, hi);   // .x = lo
    return *(uint32_t*)&h;
}

__global__ __launch_bounds__(256, 3)
void relpos_mma(const float* __restrict__ query,
                const float* __restrict__ scores,
                const float* __restrict__ rel,
                float* __restrict__ out)
{
    extern __shared__ uint32_t smem[];
    uint32_t* Qs = smem;                       // [64][QPW] packed half2
    uint32_t* Es = smem + SMEM_Q_U32;          // [192][EPW]
    float*    sG = (float*)(smem + SMEM_Q_U32 + SMEM_E_U32);  // [64][SGP]

    const int tid  = threadIdx.x;
    const int wid  = tid >> 5;
    const int lane = tid & 31;
    const int gid  = lane >> 2;
    const int tig  = lane & 3;
    const int bh = blockIdx.z;
    const int i0 = blockIdx.y * TI;
    const int j0 = blockIdx.x * TJ;
    const size_t gbase = ((size_t)bh * S_LEN + i0) * S_LEN + j0;

    // ---- Stage Q tile (64x64) as fp16; conflict-free st.64 ----
    const float* qg = query + ((size_t)bh * S_LEN + i0) * 64;
    #pragma unroll
    for (int k = 0; k < 4; ++k) {
        int idx = tid + k * 256;               // 1024 float4
        int row = idx >> 4;
        int c2  = (idx & 15) << 1;             // u32 col
        float4 v = *(const float4*)(qg + row * 64 + (c2 << 1));
        *(uint2*)(Qs + row * QPW + c2) =
            make_uint2(pack_h2(v.x, v.y), pack_h2(v.z, v.w));
    }
    // ---- Stage E tile: 192 contiguous rows (r = j-i+63 in [0,190]) ----
    const int rBase = 4096 - 63 + (j0 - i0);   // [2049,5953]; +191 < 8192
    const float* eg = rel + (size_t)rBase * 64;
    #pragma unroll
    for (int k = 0; k < 12; ++k) {
        int idx = tid + k * 256;               // 3072 float4
        int row = idx >> 4;
        int c2  = (idx & 15) << 1;
        float4 v = *(const float4*)(eg + row * 64 + (c2 << 1));
        *(uint2*)(Es + row * EPW + c2) =
            make_uint2(pack_h2(v.x, v.y), pack_h2(v.z, v.w));
    }
    __syncthreads();

    // ---- Band mainloop: warp (mi, nh); n-tiles nBase..nBase+8 ----
    const int mi = wid & 3;
    const int nh = wid >> 2;
    const int nBase = 6 - 2 * mi + 9 * nh;

    float acc[9][4];
    #pragma unroll
    for (int t = 0; t < 9; ++t) {
        acc[t][0] = 0.f; acc[t][1] = 0.f; acc[t][2] = 0.f; acc[t][3] = 0.f;
    }

    const uint32_t* aP = Qs + (16 * mi + gid) * QPW + tig;
    const uint32_t* bP = Es + (8 * nBase + gid) * EPW + tig;

    #pragma unroll
    for (int k = 0; k < 4; ++k) {              // K = 64, 16 per MMA
        uint32_t a0 = aP[0];
        uint32_t a1 = aP[8 * QPW];
        uint32_t a2 = aP[4];
        uint32_t a3 = aP[8 * QPW + 4];
        #pragma unroll
        for (int t = 0; t < 9; ++t) {
            const uint32_t* bp = bP + t * (8 * EPW);
            mma_f16(acc[t], a0, a1, a2, a3, bp[0], bp[4]);
        }
        aP += 8;                               // +16 halfs
        bP += 8;
    }

    // ---- Band store: sG[i][r_local], r_local = 8*(9nh+t)+2tig (no preds,
    //      no bounds, fragment pairs adjacent -> st.64, conflict-free) ----
    {
        const int iA = 16 * mi + gid;
        const int rl0 = 72 * nh + 2 * tig;
        float* pA = sG + iA * SGP + rl0;
        float* pB = pA + 8 * SGP;              // iB = iA + 8
        #pragma unroll
        for (int t = 0; t < 9; ++t) {
            *(float2*)(pA + 8 * t) = make_float2(acc[t][0], acc[t][1]);
            *(float2*)(pB + 8 * t) = make_float2(acc[t][2], acc[t][3]);
        }
    }
    __syncthreads();

    // ---- Epilogue: out[i][j] = scores[i][j] + sG[i][j + 15 - (i&15)] ----
    // warp w handles rows w, w+8, ..., lane-stride-1 j => LDS cf, LDG/STG
    // fully coalesced.
    #pragma unroll 2
    for (int k = 0; k < 8; ++k) {
        const int i = wid + 8 * k;
        const float* srow = scores + gbase + (size_t)i * S_LEN;
        float*       orow = out    + gbase + (size_t)i * S_LEN;
        const float* grow = sG + i * SGP + (15 - (i & 15));
        #pragma unroll
        for (int q = 0; q < 4; ++q) {
            int j = 32 * q + lane;
            orow[j] = srow[j] + grow[j];
        }
    }
}

extern "C" void kernel_launch(void* const* d_in, const int* in_sizes, int n_in,
                              void* d_out, int out_size) {
    const float* query  = nullptr;  // 2*16*2048*64   = 4194304
    const float* scores = nullptr;  // 2*16*2048*2048 = 134217728
    const float* rel    = nullptr;  // 8192*64        = 524288
    for (int i = 0; i < n_in; ++i) {
        if (in_sizes[i] == 4194304)        query  = (const float*)d_in[i];
        else if (in_sizes[i] == 134217728) scores = (const float*)d_in[i];
        else if (in_sizes[i] == 524288)    rel    = (const float*)d_in[i];
    }

    cudaFuncSetAttribute(relpos_mma,
                         cudaFuncAttributeMaxDynamicSharedMemorySize,
                         SMEM_BYTES);

    dim3 grid(S_LEN / TJ, S_LEN / TI, 32);  // (16, 32, B*H)
    relpos_mma<<<grid, 256, SMEM_BYTES>>>(query, scores, rel, (float*)d_out);
}

// round 10
// speedup vs baseline: 1.2597x; 1.2597x over previous
#include <cuda_runtime.h>
#include <cuda_fp16.h>
#include <cstdint>

// out[b,h,i,j] = scores[b,h,i,j] + sum_d q[b,h,i,d] * E[(j-i)+4096, d]
// B=2,H=16,S=2048,D=64.
//
// 64x128 (i,j) tile. G[i,r] = Q(64x64) . E_rows(192x64)^T, j = r + i - 63.
// fp16 mma.sync m16n8k16 band GEMM (warp (mi,nh): m-tile mi, 9 n-tiles from
// nBase = 6-2mi+9nh).
// R8+R9 recombined: scores tile arrives via cp.async.bulk into sS overlapping
// the mainloop (R8's win); G stored predicate-free in band layout sG[i][rl],
// rl = j + 15 - (i&15) (R9's win); merge pass sS += sG is all-scalar
// lane-stride-1 (conflict-free both sides); result leaves via cp.async.bulk
// store (TMA path, no L1tex wavefronts). sG aliases Q/E (dead after mainloop).
// 71.7KB SMEM => 3 CTAs/SM.

#define S_LEN 2048
#define TI 64
#define TJ 128
#define ER 192
#define QPW 36           // Q pitch (u32): mainloop banks 4g+t bijective
#define EPW 36
#define SGP 152          // sG pitch (floats): cf st.64 band store
#define SSP 128          // sS pitch (floats): rows contiguous 512B (bulk dst)

#define SMEM_S_U32   (TI * SSP)              // 8192
#define SMEM_QE_U32  (TI * QPW + ER * EPW)   // 9216
#define SMEM_G_U32   (TI * SGP)              // 9728  (aliases QE region)
#define SMEM_UNION_U32 (SMEM_G_U32 > SMEM_QE_U32 ? SMEM_G_U32 : SMEM_QE_U32)
#define SMEM_U32 (SMEM_S_U32 + SMEM_UNION_U32 + 8)
#define SMEM_BYTES (SMEM_U32 * 4)            // 71712

__device__ __forceinline__ uint32_t smem_u32p(const void* p) {
    uint32_t a;
    asm("{ .reg .u64 t; cvta.to.shared.u64 t, %1; cvt.u32.u64 %0, t; }"
        : "=r"(a) : "l"(p));
    return a;
}

#define MBARRIER_INIT(mbar, cnt) \
    asm volatile("mbarrier.init.shared.b64 [%0], %1;" \
                 :: "r"((uint32_t)(mbar)), "r"((uint32_t)(cnt)) : "memory")
#define MBARRIER_EXPECT_TX(mbar, bytes) \
    asm volatile("mbarrier.arrive.expect_tx.shared.b64 _, [%0], %1;" \
                 :: "r"((uint32_t)(mbar)), "r"((uint32_t)(bytes)) : "memory")
#define MBARRIER_WAIT_PARITY(mbar, par) do {                                   \
    asm volatile(                                                              \
        "{\n\t.reg .pred P1;\n\t"                                              \
        "WAIT_LOOP_%=:\n\t"                                                    \
        "mbarrier.try_wait.parity.acquire.cta.shared::cta.b64 P1, [%0], %1, 0x989680;\n\t" \
        "@P1 bra.uni WAIT_DONE_%=;\n\t"                                        \
        "bra.uni WAIT_LOOP_%=;\n\t"                                            \
        "WAIT_DONE_%=:\n\t}"                                                   \
        :: "r"((uint32_t)(mbar)), "r"((uint32_t)(par)) : "memory");            \
} while (0)
#define FENCE_PROXY_ASYNC() asm volatile("fence.proxy.async.shared::cta;" ::: "memory")

#define BULK_G2S(dst, src, bytes, mbar) \
    asm volatile("cp.async.bulk.shared::cluster.global.mbarrier::complete_tx::bytes " \
                 "[%0], [%1], %2, [%3];" \
                 :: "r"((uint32_t)(dst)), "l"(src), "r"((uint32_t)(bytes)), \
                    "r"((uint32_t)(mbar)) : "memory")
#define BULK_S2G(dst, src, bytes) \
    asm volatile("cp.async.bulk.global.shared::cta.bulk_group [%0], [%1], %2;" \
                 :: "l"(dst), "r"((uint32_t)(src)), "r"((uint32_t)(bytes)) : "memory")
#define BULK_COMMIT() asm volatile("cp.async.bulk.commit_group;" ::: "memory")
#define BULK_WAIT0()  asm volatile("cp.async.bulk.wait_group 0;" ::: "memory")

__device__ __forceinline__ void mma_f16(float* c,
                                        uint32_t a0, uint32_t a1,
                                        uint32_t a2, uint32_t a3,
                                        uint32_t b0, uint32_t b1) {
    asm volatile(
        "mma.sync.aligned.m16n8k16.row.col.f32.f16.f16.f32 "
        "{%0,%1,%2,%3}, {%4,%5,%6,%7}, {%8,%9}, {%0,%1,%2,%3};"
        : "+f"(c[0]), "+f"(c[1]), "+f"(c[2]), "+f"(c[3])
        : "r"(a0), "r"(a1), "r"(a2), "r"(a3), "r"(b0), "r"(b1));
}

__device__ __forceinline__ uint32_t pack_h2(float lo, float hi) {
    __half2 h = __floats2half2_rn(lo, hi);   // .x = lo
    return *(uint32_t*)&h;
}

__global__ __launch_bounds__(256, 3)
void relpos_mma(const float* __restrict__ query,
                const float* __restrict__ scores,
                const float* __restrict__ rel,
                float* __restrict__ out)
{
    extern __shared__ uint32_t smem[];
    float*    sS = (float*)smem;                   // [64][128] scores/result
    uint32_t* Qs = smem + SMEM_S_U32;              // [64][QPW] packed half2
    uint32_t* Es = Qs + TI * QPW;                  // [192][EPW]
    float*    sG = (float*)(smem + SMEM_S_U32);    // aliases Qs/Es after sync
    sG = (float*)(smem + SMEM_S_U32);              // [64][SGP]
    uint32_t* bar = smem + SMEM_S_U32 + SMEM_UNION_U32;
    const uint32_t barAddr = smem_u32p(bar);

    const int tid  = threadIdx.x;
    const int wid  = tid >> 5;
    const int lane = tid & 31;
    const int gid  = lane >> 2;
    const int tig  = lane & 3;
    const int bh = blockIdx.z;
    const int i0 = blockIdx.y * TI;
    const int j0 = blockIdx.x * TJ;
    const size_t gbase = ((size_t)bh * S_LEN + i0) * S_LEN + j0;

    // ---- Kick off async scores tile load (TMA engine), 64 rows x 512B ----
    if (tid == 0) {
        MBARRIER_INIT(barAddr, 1);
        FENCE_PROXY_ASYNC();
        MBARRIER_EXPECT_TX(barAddr, TI * TJ * 4);
        const uint32_t sSaddr = smem_u32p(sS);
        const float* srow = scores + gbase;
        #pragma unroll 4
        for (int il = 0; il < TI; ++il)
            BULK_G2S(sSaddr + il * (SSP * 4), srow + (size_t)il * S_LEN,
                     TJ * 4, barAddr);
    }

    // ---- Stage Q tile (64x64) as fp16; conflict-free st.64 ----
    const float* qg = query + ((size_t)bh * S_LEN + i0) * 64;
    #pragma unroll
    for (int k = 0; k < 4; ++k) {
        int idx = tid + k * 256;               // 1024 float4
        int row = idx >> 4;
        int c2  = (idx & 15) << 1;             // u32 col
        float4 v = *(const float4*)(qg + row * 64 + (c2 << 1));
        *(uint2*)(Qs + row * QPW + c2) =
            make_uint2(pack_h2(v.x, v.y), pack_h2(v.z, v.w));
    }
    // ---- Stage E tile: 192 contiguous rows (r = j-i+63 in [0,190]) ----
    const int rBase = 4096 - 63 + (j0 - i0);   // [2049,5953]; +191 < 8192
    const float* eg = rel + (size_t)rBase * 64;
    #pragma unroll
    for (int k = 0; k < 12; ++k) {
        int idx = tid + k * 256;               // 3072 float4
        int row = idx >> 4;
        int c2  = (idx & 15) << 1;
        float4 v = *(const float4*)(eg + row * 64 + (c2 << 1));
        *(uint2*)(Es + row * EPW + c2) =
            make_uint2(pack_h2(v.x, v.y), pack_h2(v.z, v.w));
    }
    __syncthreads();

    // ---- Band mainloop: warp (mi, nh); n-tiles nBase..nBase+8 ----
    const int mi = wid & 3;
    const int nh = wid >> 2;
    const int nBase = 6 - 2 * mi + 9 * nh;

    float acc[9][4];
    #pragma unroll
    for (int t = 0; t < 9; ++t) {
        acc[t][0] = 0.f; acc[t][1] = 0.f; acc[t][2] = 0.f; acc[t][3] = 0.f;
    }

    const uint32_t* aP = Qs + (16 * mi + gid) * QPW + tig;
    const uint32_t* bP = Es + (8 * nBase + gid) * EPW + tig;

    #pragma unroll
    for (int k = 0; k < 4; ++k) {              // K = 64, 16 per MMA
        uint32_t a0 = aP[0];
        uint32_t a1 = aP[8 * QPW];
        uint32_t a2 = aP[4];
        uint32_t a3 = aP[8 * QPW + 4];
        #pragma unroll
        for (int t = 0; t < 9; ++t) {
            const uint32_t* bp = bP + t * (8 * EPW);
            mma_f16(acc[t], a0, a1, a2, a3, bp[0], bp[4]);
        }
        aP += 8;                               // +16 halfs
        bP += 8;
    }
    __syncthreads();                           // Q/E dead: sG may overwrite

    // ---- Band store: sG[i][rl], rl = 72nh + 2tig + 8t (no preds, cf) ----
    {
        const int iA = 16 * mi + gid;
        const int rl0 = 72 * nh + 2 * tig;
        float* pA = sG + iA * SGP + rl0;
        float* pB = pA + 8 * SGP;              // iB = iA + 8
        #pragma unroll
        for (int t = 0; t < 9; ++t) {
            *(float2*)(pA + 8 * t) = make_float2(acc[t][0], acc[t][1]);
            *(float2*)(pB + 8 * t) = make_float2(acc[t][2], acc[t][3]);
        }
    }
    __syncthreads();

    // ---- Wait for scores, merge: sS[i][j] += sG[i][j + 15 - (i&15)] ----
    // All-scalar, lane-stride-1 on both arrays: conflict-free.
    MBARRIER_WAIT_PARITY(barAddr, 0);
    #pragma unroll
    for (int k = 0; k < 8; ++k) {
        const int i = wid + 8 * k;
        float*       srow = sS + i * SSP;
        const float* grow = sG + i * SGP + (15 - (i & 15));
        #pragma unroll
        for (int q = 0; q < 4; ++q) {
            int j = 32 * q + lane;
            srow[j] += grow[j];
        }
    }
    FENCE_PROXY_ASYNC();
    __syncthreads();

    // ---- Bulk store result rows (threads 0..63, one row each) ----
    if (tid < TI) {
        const uint32_t sSaddr = smem_u32p(sS);
        BULK_S2G(out + gbase + (size_t)tid * S_LEN,
                 sSaddr + tid * (SSP * 4), TJ * 4);
        BULK_COMMIT();
        BULK_WAIT0();
    }
    __syncthreads();
}

extern "C" void kernel_launch(void* const* d_in, const int* in_sizes, int n_in,
                              void* d_out, int out_size) {
    const float* query  = nullptr;  // 2*16*2048*64   = 4194304
    const float* scores = nullptr;  // 2*16*2048*2048 = 134217728
    const float* rel    = nullptr;  // 8192*64        = 524288
    for (int i = 0; i < n_in; ++i) {
        if (in_sizes[i] == 4194304)        query  = (const float*)d_in[i];
        else if (in_sizes[i] == 134217728) scores = (const float*)d_in[i];
        else if (in_sizes[i] == 524288)    rel    = (const float*)d_in[i];
    }

    cudaFuncSetAttribute(relpos_mma,
                         cudaFuncAttributeMaxDynamicSharedMemorySize,
                         SMEM_BYTES);

    dim3 grid(S_LEN / TJ, S_LEN / TI, 32);  // (16, 32, B*H)
    relpos_mma<<<grid, 256, SMEM_BYTES>>>(query, scores, rel, (float*)d_out);
}

// round 11
// speedup vs baseline: 1.5490x; 1.2297x over previous
#include <cuda_runtime.h>
#include <cuda_fp16.h>
#include <cstdint>

// out[b,h,i,j] = scores[b,h,i,j] + sum_d q[b,h,i,d] * E[(j-i)+4096, d]
// B=2,H=16,S=2048,D=64.
//
// 64x128 (i,j) tile. G[i,r] = Q(64x64) . E_rows(192x64)^T, j = r + i - 63.
// fp16 mma.sync m16n8k16 band GEMM (warp (mi,nh): m-tile mi, 9 n-tiles from
// nBase = 6-2mi+9nh).
// R11 = R10 with the serialized back-end removed: scores still arrive via
// cp.async.bulk into sS overlapping the mainloop; G still stored predicate-
// free into band layout sG[i][rl], rl = j + 15 - (i&15); but the epilogue is
// now a single per-warp pass  out[i][j] = sS[i][j] + sG[i][rl]  via coalesced
// STG.32 (1 wavefront per warp-instr). Deleted: sS writeback, proxy fence,
// bulk store, BULK_WAIT0 tail, two __syncthreads. CTA retires with STGs
// draining. sG aliases Q/E (dead after mainloop). 71.7KB SMEM => 3 CTAs/SM.

#define S_LEN 2048
#define TI 64
#define TJ 128
#define ER 192
#define QPW 36           // Q pitch (u32): mainloop banks 4g+t bijective
#define EPW 36
#define SGP 152          // sG pitch (floats): cf st.64 band store
#define SSP 128          // sS pitch (floats): rows contiguous 512B (bulk dst)

#define SMEM_S_U32   (TI * SSP)              // 8192
#define SMEM_QE_U32  (TI * QPW + ER * EPW)   // 9216
#define SMEM_G_U32   (TI * SGP)              // 9728  (aliases QE region)
#define SMEM_UNION_U32 (SMEM_G_U32 > SMEM_QE_U32 ? SMEM_G_U32 : SMEM_QE_U32)
#define SMEM_U32 (SMEM_S_U32 + SMEM_UNION_U32 + 8)
#define SMEM_BYTES (SMEM_U32 * 4)            // 71712

__device__ __forceinline__ uint32_t smem_u32p(const void* p) {
    uint32_t a;
    asm("{ .reg .u64 t; cvta.to.shared.u64 t, %1; cvt.u32.u64 %0, t; }"
        : "=r"(a) : "l"(p));
    return a;
}

#define MBARRIER_INIT(mbar, cnt) \
    asm volatile("mbarrier.init.shared.b64 [%0], %1;" \
                 :: "r"((uint32_t)(mbar)), "r"((uint32_t)(cnt)) : "memory")
#define MBARRIER_EXPECT_TX(mbar, bytes) \
    asm volatile("mbarrier.arrive.expect_tx.shared.b64 _, [%0], %1;" \
                 :: "r"((uint32_t)(mbar)), "r"((uint32_t)(bytes)) : "memory")
#define MBARRIER_WAIT_PARITY(mbar, par) do {                                   \
    asm volatile(                                                              \
        "{\n\t.reg .pred P1;\n\t"                                              \
        "WAIT_LOOP_%=:\n\t"                                                    \
        "mbarrier.try_wait.parity.acquire.cta.shared::cta.b64 P1, [%0], %1, 0x989680;\n\t" \
        "@P1 bra.uni WAIT_DONE_%=;\n\t"                                        \
        "bra.uni WAIT_LOOP_%=;\n\t"                                            \
        "WAIT_DONE_%=:\n\t}"                                                   \
        :: "r"((uint32_t)(mbar)), "r"((uint32_t)(par)) : "memory");            \
} while (0)
#define FENCE_PROXY_ASYNC() asm volatile("fence.proxy.async.shared::cta;" ::: "memory")

#define BULK_G2S(dst, src, bytes, mbar) \
    asm volatile("cp.async.bulk.shared::cluster.global.mbarrier::complete_tx::bytes " \
                 "[%0], [%1], %2, [%3];" \
                 :: "r"((uint32_t)(dst)), "l"(src), "r"((uint32_t)(bytes)), \
                    "r"((uint32_t)(mbar)) : "memory")

__device__ __forceinline__ void mma_f16(float* c,
                                        uint32_t a0, uint32_t a1,
                                        uint32_t a2, uint32_t a3,
                                        uint32_t b0, uint32_t b1) {
    asm volatile(
        "mma.sync.aligned.m16n8k16.row.col.f32.f16.f16.f32 "
        "{%0,%1,%2,%3}, {%4,%5,%6,%7}, {%8,%9}, {%0,%1,%2,%3};"
        : "+f"(c[0]), "+f"(c[1]), "+f"(c[2]), "+f"(c[3])
        : "r"(a0), "r"(a1), "r"(a2), "r"(a3), "r"(b0), "r"(b1));
}

__device__ __forceinline__ uint32_t pack_h2(float lo, float hi) {
    __half2 h = __floats2half2_rn(lo, hi);   // .x = lo
    return *(uint32_t*)&h;
}

__global__ __launch_bounds__(256, 3)
void relpos_mma(const float* __restrict__ query,
                const float* __restrict__ scores,
                const float* __restrict__ rel,
                float* __restrict__ out)
{
    extern __shared__ uint32_t smem[];
    float*    sS = (float*)smem;                   // [64][128] scores tile
    uint32_t* Qs = smem + SMEM_S_U32;              // [64][QPW] packed half2
    uint32_t* Es = Qs + TI * QPW;                  // [192][EPW]
    float*    sG = (float*)(smem + SMEM_S_U32);    // [64][SGP] aliases Qs/Es
    uint32_t* bar = smem + SMEM_S_U32 + SMEM_UNION_U32;
    const uint32_t barAddr = smem_u32p(bar);

    const int tid  = threadIdx.x;
    const int wid  = tid >> 5;
    const int lane = tid & 31;
    const int gid  = lane >> 2;
    const int tig  = lane & 3;
    const int bh = blockIdx.z;
    const int i0 = blockIdx.y * TI;
    const int j0 = blockIdx.x * TJ;
    const size_t gbase = ((size_t)bh * S_LEN + i0) * S_LEN + j0;

    // ---- Kick off async scores tile load (TMA engine), 64 rows x 512B ----
    if (tid == 0) {
        MBARRIER_INIT(barAddr, 1);
        FENCE_PROXY_ASYNC();
        MBARRIER_EXPECT_TX(barAddr, TI * TJ * 4);
        const uint32_t sSaddr = smem_u32p(sS);
        const float* srow = scores + gbase;
        #pragma unroll 4
        for (int il = 0; il < TI; ++il)
            BULK_G2S(sSaddr + il * (SSP * 4), srow + (size_t)il * S_LEN,
                     TJ * 4, barAddr);
    }

    // ---- Stage Q tile (64x64) as fp16; conflict-free st.64 ----
    const float* qg = query + ((size_t)bh * S_LEN + i0) * 64;
    #pragma unroll
    for (int k = 0; k < 4; ++k) {
        int idx = tid + k * 256;               // 1024 float4
        int row = idx >> 4;
        int c2  = (idx & 15) << 1;             // u32 col
        float4 v = *(const float4*)(qg + row * 64 + (c2 << 1));
        *(uint2*)(Qs + row * QPW + c2) =
            make_uint2(pack_h2(v.x, v.y), pack_h2(v.z, v.w));
    }
    // ---- Stage E tile: 192 contiguous rows (r = j-i+63 in [0,190]) ----
    const int rBase = 4096 - 63 + (j0 - i0);   // [2049,5953]; +191 < 8192
    const float* eg = rel + (size_t)rBase * 64;
    #pragma unroll
    for (int k = 0; k < 12; ++k) {
        int idx = tid + k * 256;               // 3072 float4
        int row = idx >> 4;
        int c2  = (idx & 15) << 1;
        float4 v = *(const float4*)(eg + row * 64 + (c2 << 1));
        *(uint2*)(Es + row * EPW + c2) =
            make_uint2(pack_h2(v.x, v.y), pack_h2(v.z, v.w));
    }
    __syncthreads();

    // ---- Band mainloop: warp (mi, nh); n-tiles nBase..nBase+8 ----
    const int mi = wid & 3;
    const int nh = wid >> 2;
    const int nBase = 6 - 2 * mi + 9 * nh;

    float acc[9][4];
    #pragma unroll
    for (int t = 0; t < 9; ++t) {
        acc[t][0] = 0.f; acc[t][1] = 0.f; acc[t][2] = 0.f; acc[t][3] = 0.f;
    }

    const uint32_t* aP = Qs + (16 * mi + gid) * QPW + tig;
    const uint32_t* bP = Es + (8 * nBase + gid) * EPW + tig;

    #pragma unroll
    for (int k = 0; k < 4; ++k) {              // K = 64, 16 per MMA
        uint32_t a0 = aP[0];
        uint32_t a1 = aP[8 * QPW];
        uint32_t a2 = aP[4];
        uint32_t a3 = aP[8 * QPW + 4];
        #pragma unroll
        for (int t = 0; t < 9; ++t) {
            const uint32_t* bp = bP + t * (8 * EPW);
            mma_f16(acc[t], a0, a1, a2, a3, bp[0], bp[4]);
        }
        aP += 8;                               // +16 halfs
        bP += 8;
    }
    __syncthreads();                           // Q/E dead: sG may overwrite

    // ---- Band store: sG[i][rl], rl = 72nh + 2tig + 8t (no preds, cf) ----
    {
        const int iA = 16 * mi + gid;
        const int rl0 = 72 * nh + 2 * tig;
        float* pA = sG + iA * SGP + rl0;
        float* pB = pA + 8 * SGP;              // iB = iA + 8
        #pragma unroll
        for (int t = 0; t < 9; ++t) {
            *(float2*)(pA + 8 * t) = make_float2(acc[t][0], acc[t][1]);
            *(float2*)(pB + 8 * t) = make_float2(acc[t][2], acc[t][3]);
        }
    }
    MBARRIER_WAIT_PARITY(barAddr, 0);          // scores ready (usually no-op)
    __syncthreads();                           // sG visible cross-warp

    // ---- Epilogue: out[i][j] = sS[i][j] + sG[i][j + 15 - (i&15)] ----
    // Per-warp independent; scalar stride-1 LDS (cf both arrays), coalesced
    // STG.32 (1 wavefront per warp-instr). No writeback, no bulk tail.
    #pragma unroll
    for (int k = 0; k < 8; ++k) {
        const int i = wid + 8 * k;
        const float* srow = sS + i * SSP;
        const float* grow = sG + i * SGP + (15 - (i & 15));
        float* orow = out + gbase + (size_t)i * S_LEN;
        #pragma unroll
        for (int q = 0; q < 4; ++q) {
            int j = 32 * q + lane;
            orow[j] = srow[j] + grow[j];
        }
    }
}

extern "C" void kernel_launch(void* const* d_in, const int* in_sizes, int n_in,
                              void* d_out, int out_size) {
    const float* query  = nullptr;  // 2*16*2048*64   = 4194304
    const float* scores = nullptr;  // 2*16*2048*2048 = 134217728
    const float* rel    = nullptr;  // 8192*64        = 524288
    for (int i = 0; i < n_in; ++i) {
        if (in_sizes[i] == 4194304)        query  = (const float*)d_in[i];
        else if (in_sizes[i] == 134217728) scores = (const float*)d_in[i];
        else if (in_sizes[i] == 524288)    rel    = (const float*)d_in[i];
    }

    cudaFuncSetAttribute(relpos_mma,
                         cudaFuncAttributeMaxDynamicSharedMemorySize,
                         SMEM_BYTES);

    dim3 grid(S_LEN / TJ, S_LEN / TI, 32);  // (16, 32, B*H)
    relpos_mma<<<grid, 256, SMEM_BYTES>>>(query, scores, rel, (float*)d_out);
}

// round 12
// speedup vs baseline: 1.6883x; 1.0899x over previous
#include <cuda_runtime.h>
#include <cuda_fp16.h>
#include <cstdint>

// out[b,h,i,j] = scores[b,h,i,j] + sum_d q[b,h,i,d] * E[(j-i)+4096, d]
// B=2,H=16,S=2048,D=64.
//
// 64x128 (i,j) tile. G[i,r] = Q(64x64) . E_rows(192x64)^T, j = r + i - 63.
// fp16 mma.sync m16n8k16.
// R12 vs R11 (two L1-byte reductions, code-disjoint):
//  1) Disjoint warp partition: warp (ng=wid&3, mh=wid>>2) owns n-tiles
//     [6ng,6ng+5] x m-tiles {2mh,2mh+1} = 12 uniform slots. b-LDS/warp/k
//     36->12 (kills the 6x n-tile re-read), a 4->8. Out-of-band slots compute
//     garbage (in-bounds reads) and are skipped at store time (warp-uniform
//     branch). Store col = 8n+2tig+16mi-48 in [0,142] for valid slots; the
//     epilogue read is unchanged from R11: sG[i][j+15-(i&15)], pitch 148.
//  2) Pre-kernel converts Q,E to fp16 pitch-36 scratch (same banking as R11);
//     main kernel stages them with ONE cp.async.bulk each (TMA path, no L1tex
//     wavefronts, no cvt). Separate mbarriers: QE waited before mainloop,
//     scores before epilogue (keeps the R8/R11 overlap).
// SMEM 70.7KB => 3 CTAs/SM.

#define S_LEN 2048
#define TI 64
#define TJ 128
#define ER 192
#define PW 36            // Q/E pitch (u32); mainloop banks 4g+t bijective
#define SGP 148          // sG pitch (floats)
#define SSP 128          // sS pitch (floats), bulk dst rows contiguous

#define SMEM_S_U32   (TI * SSP)              // 8192
#define SMEM_QE_U32  (TI * PW + ER * PW)     // 9216
#define SMEM_G_U32   (TI * SGP)              // 9472 (aliases QE region)
#define SMEM_UNION_U32 (SMEM_G_U32 > SMEM_QE_U32 ? SMEM_G_U32 : SMEM_QE_U32)
#define SMEM_U32 (SMEM_S_U32 + SMEM_UNION_U32 + 8)
#define SMEM_BYTES (SMEM_U32 * 4)            // 70688

// fp16 scratch, pitch 36 u32/row (cols 32..35 pad, never read)
__device__ uint32_t g_qsc[32 * 2048 * PW];   // 9.4 MB
__device__ uint32_t g_esc[8192 * PW];        // 1.2 MB

__device__ __forceinline__ uint32_t smem_u32p(const void* p) {
    uint32_t a;
    asm("{ .reg .u64 t; cvta.to.shared.u64 t, %1; cvt.u32.u64 %0, t; }"
        : "=r"(a) : "l"(p));
    return a;
}

#define MBARRIER_INIT(mbar, cnt) \
    asm volatile("mbarrier.init.shared.b64 [%0], %1;" \
                 :: "r"((uint32_t)(mbar)), "r"((uint32_t)(cnt)) : "memory")
#define MBARRIER_EXPECT_TX(mbar, bytes) \
    asm volatile("mbarrier.arrive.expect_tx.shared.b64 _, [%0], %1;" \
                 :: "r"((uint32_t)(mbar)), "r"((uint32_t)(bytes)) : "memory")
#define MBARRIER_WAIT_PARITY(mbar, par) do {                                   \
    asm volatile(                                                              \
        "{\n\t.reg .pred P1;\n\t"                                              \
        "WAIT_LOOP_%=:\n\t"                                                    \
        "mbarrier.try_wait.parity.acquire.cta.shared::cta.b64 P1, [%0], %1, 0x989680;\n\t" \
        "@P1 bra.uni WAIT_DONE_%=;\n\t"                                        \
        "bra.uni WAIT_LOOP_%=;\n\t"                                            \
        "WAIT_DONE_%=:\n\t}"                                                   \
        :: "r"((uint32_t)(mbar)), "r"((uint32_t)(par)) : "memory");            \
} while (0)
#define FENCE_PROXY_ASYNC() asm volatile("fence.proxy.async.shared::cta;" ::: "memory")

#define BULK_G2S(dst, src, bytes, mbar) \
    asm volatile("cp.async.bulk.shared::cluster.global.mbarrier::complete_tx::bytes " \
                 "[%0], [%1], %2, [%3];" \
                 :: "r"((uint32_t)(dst)), "l"(src), "r"((uint32_t)(bytes)), \
                    "r"((uint32_t)(mbar)) : "memory")

__device__ __forceinline__ void mma_f16(float* c,
                                        uint32_t a0, uint32_t a1,
                                        uint32_t a2, uint32_t a3,
                                        uint32_t b0, uint32_t b1) {
    asm volatile(
        "mma.sync.aligned.m16n8k16.row.col.f32.f16.f16.f32 "
        "{%0,%1,%2,%3}, {%4,%5,%6,%7}, {%8,%9}, {%0,%1,%2,%3};"
        : "+f"(c[0]), "+f"(c[1]), "+f"(c[2]), "+f"(c[3])
        : "r"(a0), "r"(a1), "r"(a2), "r"(a3), "r"(b0), "r"(b1));
}

__device__ __forceinline__ uint32_t pack_h2(float lo, float hi) {
    __half2 h = __floats2half2_rn(lo, hi);
    return *(uint32_t*)&h;
}

// ---- Pre-kernel: fp32 -> fp16 scratch (pitch 36) ----
#define Q_U32 (32 * 2048 * 32)
#define E_U32 (8192 * 32)
__global__ __launch_bounds__(256)
void convert_kernel(const float* __restrict__ query,
                    const float* __restrict__ rel)
{
    int idx = blockIdx.x * 256 + threadIdx.x;
    if (idx < Q_U32) {
        int row = idx >> 5, c = idx & 31;
        float2 v = *(const float2*)(query + (size_t)row * 64 + 2 * c);
        g_qsc[row * PW + c] = pack_h2(v.x, v.y);
    } else if (idx < Q_U32 + E_U32) {
        int e = idx - Q_U32;
        int row = e >> 5, c = e & 31;
        float2 v = *(const float2*)(rel + (size_t)row * 64 + 2 * c);
        g_esc[row * PW + c] = pack_h2(v.x, v.y);
    }
}

__global__ __launch_bounds__(256, 3)
void relpos_mma(const float* __restrict__ scores,
                float* __restrict__ out)
{
    extern __shared__ uint32_t smem[];
    float*    sS = (float*)smem;                   // [64][128] scores tile
    uint32_t* Qs = smem + SMEM_S_U32;              // [64][PW] packed half2
    uint32_t* Es = Qs + TI * PW;                   // [192][PW]
    float*    sG = (float*)(smem + SMEM_S_U32);    // [64][SGP] aliases Qs/Es
    uint32_t* bars = smem + SMEM_S_U32 + SMEM_UNION_U32;
    const uint32_t barQE = smem_u32p(bars);
    const uint32_t barS  = barQE + 8;

    const int tid  = threadIdx.x;
    const int wid  = tid >> 5;
    const int lane = tid & 31;
    const int gid  = lane >> 2;
    const int tig  = lane & 3;
    const int bh = blockIdx.z;
    const int i0 = blockIdx.y * TI;
    const int j0 = blockIdx.x * TJ;
    const size_t gbase = ((size_t)bh * S_LEN + i0) * S_LEN + j0;

    if (tid == 0) {
        MBARRIER_INIT(barQE, 1);
        MBARRIER_INIT(barS, 1);
        FENCE_PROXY_ASYNC();
    }
    __syncthreads();   // barriers initialized before anyone waits

    if (tid == 0) {
        // Q + E tiles: single contiguous bulk copies from fp16 scratch
        MBARRIER_EXPECT_TX(barQE, (TI + ER) * PW * 4);
        const uint32_t* qsrc = g_qsc + ((size_t)bh * S_LEN + i0) * PW;
        BULK_G2S(smem_u32p(Qs), qsrc, TI * PW * 4, barQE);
        const int rBase = 4096 - 63 + (j0 - i0);   // [2049,5953]; +191 < 8192
        const uint32_t* esrc = g_esc + (size_t)rBase * PW;
        BULK_G2S(smem_u32p(Es), esrc, ER * PW * 4, barQE);
        // Scores tile: 64 row copies (512B each)
        MBARRIER_EXPECT_TX(barS, TI * TJ * 4);
        const uint32_t sSaddr = smem_u32p(sS);
        const float* srow = scores + gbase;
        #pragma unroll 4
        for (int il = 0; il < TI; ++il)
            BULK_G2S(sSaddr + il * (SSP * 4), srow + (size_t)il * S_LEN,
                     TJ * 4, barS);
    }

    // ---- Wait Q/E, then band mainloop ----
    MBARRIER_WAIT_PARITY(barQE, 0);

    // warp (ng, mh): n-tiles 6ng..6ng+5, m-tiles {2mh, 2mh+1}
    const int ng = wid & 3;
    const int mh = wid >> 2;

    float acc[12][4];
    #pragma unroll
    for (int s = 0; s < 12; ++s) {
        acc[s][0] = 0.f; acc[s][1] = 0.f; acc[s][2] = 0.f; acc[s][3] = 0.f;
    }

    const uint32_t* aP0 = Qs + (32 * mh + gid) * PW + tig;       // m-tile 2mh
    const uint32_t* aP1 = aP0 + 16 * PW;                         // m-tile 2mh+1
    const uint32_t* bP  = Es + (48 * ng + gid) * PW + tig;

    #pragma unroll
    for (int k = 0; k < 4; ++k) {              // K = 64, 16 per MMA
        uint32_t a00 = aP0[0], a01 = aP0[8 * PW], a02 = aP0[4], a03 = aP0[8 * PW + 4];
        uint32_t a10 = aP1[0], a11 = aP1[8 * PW], a12 = aP1[4], a13 = aP1[8 * PW + 4];
        #pragma unroll
        for (int t = 0; t < 6; ++t) {
            const uint32_t* bp = bP + t * (8 * PW);
            uint32_t b0 = bp[0], b1 = bp[4];
            mma_f16(acc[t],     a00, a01, a02, a03, b0, b1);
            mma_f16(acc[6 + t], a10, a11, a12, a13, b0, b1);
        }
        aP0 += 8; aP1 += 8; bP += 8;           // +16 halfs
    }
    __syncthreads();                           // Q/E dead: sG may overwrite

    // ---- Band store (valid slots only; warp-uniform branch) ----
    // slot (mt, t): mi = 2mh+mt, n = 6ng+t; valid iff 6-2mi <= n <= 23-2mi.
    // col = 8n + 2tig + 16mi - 48  (in [0,142] for valid slots; even -> st.64)
    #pragma unroll
    for (int mt = 0; mt < 2; ++mt) {
        const int mi = 2 * mh + mt;
        #pragma unroll
        for (int t = 0; t < 6; ++t) {
            const int n = 6 * ng + t;
            if (n >= 6 - 2 * mi && n <= 23 - 2 * mi) {
                const int col = 8 * n + 2 * tig + 16 * mi - 48;
                float* pA = sG + (16 * mi + gid) * SGP + col;
                float* pB = pA + 8 * SGP;
                *(float2*)pA = make_float2(acc[mt * 6 + t][0], acc[mt * 6 + t][1]);
                *(float2*)pB = make_float2(acc[mt * 6 + t][2], acc[mt * 6 + t][3]);
            }
        }
    }
    MBARRIER_WAIT_PARITY(barS, 0);             // scores ready (usually no-op)
    __syncthreads();                           // sG visible cross-warp

    // ---- Epilogue: out[i][j] = sS[i][j] + sG[i][j + 15 - (i&15)] ----
    #pragma unroll
    for (int k = 0; k < 8; ++k) {
        const int i = wid + 8 * k;
        const float* srow = sS + i * SSP;
        const float* grow = sG + i * SGP + (15 - (i & 15));
        float* orow = out + gbase + (size_t)i * S_LEN;
        #pragma unroll
        for (int q = 0; q < 4; ++q) {
            int j = 32 * q + lane;
            orow[j] = srow[j] + grow[j];
        }
    }
}

extern "C" void kernel_launch(void* const* d_in, const int* in_sizes, int n_in,
                              void* d_out, int out_size) {
    const float* query  = nullptr;  // 2*16*2048*64   = 4194304
    const float* scores = nullptr;  // 2*16*2048*2048 = 134217728
    const float* rel    = nullptr;  // 8192*64        = 524288
    for (int i = 0; i < n_in; ++i) {
        if (in_sizes[i] == 4194304)        query  = (const float*)d_in[i];
        else if (in_sizes[i] == 134217728) scores = (const float*)d_in[i];
        else if (in_sizes[i] == 524288)    rel    = (const float*)d_in[i];
    }

    // Pre-convert Q, E to fp16 scratch (every launch; deterministic)
    int convN = (Q_U32 + E_U32 + 255) / 256;
    convert_kernel<<<convN, 256>>>(query, rel);

    cudaFuncSetAttribute(relpos_mma,
                         cudaFuncAttributeMaxDynamicSharedMemorySize,
                         SMEM_BYTES);

    dim3 grid(S_LEN / TJ, S_LEN / TI, 32);  // (16, 32, B*H)
    relpos_mma<<<grid, 256, SMEM_BYTES>>>(scores, (float*)d_out);
}